// round 4
// baseline (speedup 1.0000x reference)
#include <cuda_runtime.h>
#include <cstdint>

// Problem constants
#define BATCH 32
#define CHAN  256
#define HW    56
#define NW    (256*256*9)   // weight elements

// Scratch (device globals; no allocation allowed)
__device__ float g_wqT[9 * 256 * 256];  // [(ci*9+k)][co]  quantized, transposed
__device__ float g_inv[256];
__device__ float g_bias[256];
__device__ int   g_max_bits;

// ---------------------------------------------------------------------------
// XLA/Eigen rational tanh replica (bit-matching jnp.tanh on f32 is critical:
// a single 4-bit weight-bin flip injects ~2e-3 rel_err into the output).
// ---------------------------------------------------------------------------
__device__ __forceinline__ float xla_tanh(float x) {
    float ax = fabsf(x);
    if (ax < 0.0004f) return x;
    float xc = fminf(fmaxf(x, -7.90531110763549805f), 7.90531110763549805f);
    float x2 = xc * xc;
    float p = -2.76076847742355e-16f;
    p = fmaf(p, x2, 2.00018790482477e-13f);
    p = fmaf(p, x2, -8.60467152213735e-11f);
    p = fmaf(p, x2, 5.12229709037114e-08f);
    p = fmaf(p, x2, 1.48572235717979e-05f);
    p = fmaf(p, x2, 6.37261928875436e-04f);
    p = fmaf(p, x2, 4.89352455891786e-03f);
    p = p * xc;
    float q = 1.19825839466702e-06f;
    q = fmaf(q, x2, 1.18534705686654e-04f);
    q = fmaf(q, x2, 2.26843463243900e-03f);
    q = fmaf(q, x2, 4.89352518554385e-03f);
    return p / q;
}

// ---------------------------------------------------------------------------
// k_init: reset the max-reduction scalar; precompute BN inv/bias per channel
// ---------------------------------------------------------------------------
__global__ void k_init(const float* __restrict__ gamma, const float* __restrict__ beta,
                       const float* __restrict__ mean,  const float* __restrict__ var) {
    int t = threadIdx.x;
    if (t == 0) g_max_bits = 0;
    float inv = gamma[t] / sqrtf(var[t] + 1e-5f);
    g_inv[t]  = inv;
    g_bias[t] = beta[t] - mean[t] * inv;
}

// ---------------------------------------------------------------------------
// k_max: global max |tanh(w)| via block reduce + atomicMax on float bits
// (all values >= 0 so int compare is monotone)
// ---------------------------------------------------------------------------
__global__ void k_max(const float* __restrict__ w) {
    __shared__ float sm[256];
    float m = 0.f;
    for (int i = blockIdx.x * 256 + threadIdx.x; i < NW; i += gridDim.x * 256)
        m = fmaxf(m, fabsf(xla_tanh(w[i])));
    sm[threadIdx.x] = m;
    __syncthreads();
    for (int s = 128; s > 0; s >>= 1) {
        if (threadIdx.x < s) sm[threadIdx.x] = fmaxf(sm[threadIdx.x], sm[threadIdx.x + s]);
        __syncthreads();
    }
    if (threadIdx.x == 0) atomicMax(&g_max_bits, __float_as_int(sm[0]));
}

// ---------------------------------------------------------------------------
// k_quant: DoReFa 4-bit quantize + transpose to [(ci*9+k)][co] for coalesced
// smem fills in the conv kernel.
// ---------------------------------------------------------------------------
__global__ void k_quant(const float* __restrict__ w) {
    int i = blockIdx.x * blockDim.x + threadIdx.x;
    if (i >= NW) return;
    float M = __int_as_float(g_max_bits);
    float t = xla_tanh(w[i]);
    t = t / (2.0f * M) + 0.5f;          // mirror ref op order exactly
    float q  = rintf(t * 15.0f);        // round-half-even, like jnp.round
    float tq = q / 15.0f;
    float wq = 2.0f * tq - 1.0f;
    int co = i / 2304;                  // weight is [co][ci][3][3]
    int r  = i % 2304;                  // ci*9 + k
    g_wqT[r * 256 + co] = wq;
}

// ---------------------------------------------------------------------------
// k_conv: direct 3x3 conv, fused BN + PACT epilogue.
// Block tile: 128 co x (8h x 8w). 128 threads; thread tile 8 co x 8 w-pixels.
// C_in chunked by 8 through shared memory.
// ---------------------------------------------------------------------------
__global__ __launch_bounds__(128, 2)
void k_conv(const float* __restrict__ x, const float* __restrict__ alpha,
            float* __restrict__ out) {
    __shared__ float sw[8 * 9 * 128];     // [ci][k][co]  36 KB
    __shared__ float sx[8][10][12];       // [ci][row][col], cols padded to 12 (f4-aligned)

    const int bx     = blockIdx.x;        // 0..97
    const int n      = blockIdx.y;        // batch
    const int co_blk = bx / 49;
    const int hw     = bx % 49;
    const int h0     = (hw / 7) * 8;
    const int w0     = (hw % 7) * 8;
    const int co0    = co_blk * 128;

    const int t    = threadIdx.x;
    const int co_g = t >> 3;              // 0..15 (8 co each)
    const int row  = t & 7;               // 0..7  (h within tile)

    float acc[8][8];
#pragma unroll
    for (int j = 0; j < 8; j++)
#pragma unroll
        for (int p = 0; p < 8; p++) acc[j][p] = 0.f;

    const float* xn = x + (size_t)n * CHAN * HW * HW;

    for (int ci0 = 0; ci0 < CHAN; ci0 += 8) {
        __syncthreads();
        // --- weights: 8 ci * 9 taps * 128 co = 2304 float4, coalesced ---
        {
            const float* gw = g_wqT + ci0 * 9 * 256 + co0;
#pragma unroll
            for (int l = 0; l < 18; l++) {
                int idx4 = t + l * 128;          // 0..2303
                int rk   = idx4 >> 5;            // (ci*9+k) 0..71
                int c4   = idx4 & 31;
                ((float4*)sw)[idx4] = *(const float4*)(gw + rk * 256 + c4 * 4);
            }
        }
        // --- input patch: 8 ci x 10 x 10 (zero padded, cols padded to 12) ---
#pragma unroll
        for (int l = 0; l < 8; l++) {
            int idx = t + l * 128;
            if (idx < 960) {
                int ci = idx / 120;
                int r2 = idx % 120;
                int rr = r2 / 12, cc = r2 % 12;
                int hh = h0 - 1 + rr, ww = w0 - 1 + cc;
                float v = 0.f;
                if (cc < 10 && (unsigned)hh < 56u && (unsigned)ww < 56u)
                    v = xn[((ci0 + ci) * 56 + hh) * 56 + ww];
                sx[ci][rr][cc] = v;
            }
        }
        __syncthreads();

        for (int ci = 0; ci < 8; ci++) {
#pragma unroll
            for (int kh = 0; kh < 3; kh++) {
                float xr[12];
                const float4* xp = (const float4*)&sx[ci][row + kh][0];
                float4 a0 = xp[0], a1 = xp[1], a2 = xp[2];
                xr[0] = a0.x; xr[1] = a0.y; xr[2]  = a0.z; xr[3]  = a0.w;
                xr[4] = a1.x; xr[5] = a1.y; xr[6]  = a1.z; xr[7]  = a1.w;
                xr[8] = a2.x; xr[9] = a2.y; xr[10] = a2.z; xr[11] = a2.w;
                const float* swp = sw + (ci * 9 + kh * 3) * 128 + co_g * 8;
#pragma unroll
                for (int kw = 0; kw < 3; kw++) {
                    float4 b0 = *(const float4*)(swp + kw * 128);
                    float4 b1 = *(const float4*)(swp + kw * 128 + 4);
                    float wv[8] = {b0.x, b0.y, b0.z, b0.w, b1.x, b1.y, b1.z, b1.w};
#pragma unroll
                    for (int j = 0; j < 8; j++)
#pragma unroll
                        for (int p = 0; p < 8; p++)
                            acc[j][p] = fmaf(wv[j], xr[kw + p], acc[j][p]);
                }
            }
        }
    }

    // --- epilogue: BN + PACT (clip to [0,a], round to a/15 grid) ---
    const float a    = alpha[0];
    const float step = a / 15.0f;         // ref computes (a/n) once
#pragma unroll
    for (int j = 0; j < 8; j++) {
        int co = co0 + co_g * 8 + j;
        float inv = g_inv[co], bi = g_bias[co];
        float o[8];
#pragma unroll
        for (int p = 0; p < 8; p++) {
            float v = acc[j][p] * inv + bi;
            v = fminf(fmaxf(v, 0.f), a);
            float q = rintf(v * 15.0f / a);   // IEEE div to mirror jnp
            o[p] = q * step;
        }
        float* op = out + (((size_t)n * 256 + co) * 56 + (h0 + row)) * 56 + w0;
        ((float4*)op)[0] = make_float4(o[0], o[1], o[2], o[3]);
        ((float4*)op)[1] = make_float4(o[4], o[5], o[6], o[7]);
    }
}

// ---------------------------------------------------------------------------
extern "C" void kernel_launch(void* const* d_in, const int* in_sizes, int n_in,
                              void* d_out, int out_size) {
    const float* x     = (const float*)d_in[0];
    const float* w     = (const float*)d_in[1];
    const float* gamma = (const float*)d_in[2];
    const float* beta  = (const float*)d_in[3];
    const float* mean  = (const float*)d_in[4];
    const float* var   = (const float*)d_in[5];
    const float* alpha = (const float*)d_in[6];
    float* out = (float*)d_out;

    k_init<<<1, 256>>>(gamma, beta, mean, var);
    k_max<<<148, 256>>>(w);
    k_quant<<<2304, 256>>>(w);

    dim3 grid(98, 32);   // (2 co blocks * 49 spatial tiles, batch)
    k_conv<<<grid, 128>>>(x, alpha, out);
}

// round 6
// speedup vs baseline: 4.2338x; 4.2338x over previous
#include <cuda_runtime.h>
#include <cuda_fp16.h>
#include <cstdint>

#define NW (256*256*9)

// ---------------- scratch (device globals; no allocation allowed) ----------
__device__ float  g_inv[256];
__device__ float  g_bias[256];
__device__ int    g_max_bits;
// B blocks: [tap*8+chunk] x contiguous 16KB: [co][32ci], 16B-unit xor-swizzled
__device__ __align__(16) __half g_w15[9*8*256*32];
__device__ __align__(16) __half g_xh[32*3136*256];    // [n][pix][ci] hi plane
__device__ __align__(16) __half g_xl[32*3136*256];    // [n][pix][ci] lo plane

// ---------------- PTX helpers ---------------------------------------------
__device__ __forceinline__ uint32_t smem_u32(const void* p) {
    uint32_t a;
    asm("{ .reg .u64 t; cvta.to.shared.u64 t, %1; cvt.u32.u64 %0, t; }" : "=r"(a) : "l"(p));
    return a;
}
#define MBARRIER_INIT(mb, c) \
    asm volatile("mbarrier.init.shared.b64 [%0], %1;" :: "r"((uint32_t)(mb)), "r"((uint32_t)(c)) : "memory")
#define MBARRIER_EXPECT_TX(mb, b) \
    asm volatile("mbarrier.arrive.expect_tx.shared.b64 _, [%0], %1;" :: "r"((uint32_t)(mb)), "r"((uint32_t)(b)) : "memory")
#define MBARRIER_WAIT_PARITY(mb, ph) do { \
    uint32_t _m = (uint32_t)(mb), _p = (uint32_t)(ph), _d; \
    asm volatile("{ .reg .pred p; mbarrier.try_wait.parity.acquire.cta.shared::cta.b64 p, [%1], %2; selp.b32 %0,1,0,p; }" \
        : "=r"(_d) : "r"(_m), "r"(_p) : "memory"); \
    if (!_d) { \
        asm volatile("{ .reg .pred P1; WL_%=: mbarrier.try_wait.parity.acquire.cta.shared::cta.b64 P1, [%0], %1, 0x989680; @P1 bra.uni WD_%=; bra.uni WL_%=; WD_%=: }" \
            :: "r"(_m), "r"(_p) : "memory"); \
    } } while (0)
#define CP_ASYNC16Z(sdst, gsrc, sz) \
    asm volatile("cp.async.cg.shared.global [%0], [%1], 16, %2;" :: "r"(sdst), "l"(gsrc), "r"(sz) : "memory")
#define CP_ASYNC_COMMIT() asm volatile("cp.async.commit_group;" ::: "memory")
#define CP_ASYNC_WAIT1()  asm volatile("cp.async.wait_group 1;" ::: "memory")
#define CP_ASYNC_WAIT0()  asm volatile("cp.async.wait_group 0;" ::: "memory")
#define CP_BULK(sdst, gsrc, bytes, mb) \
    asm volatile("cp.async.bulk.shared::cluster.global.mbarrier::complete_tx::bytes [%0], [%1], %2, [%3];" \
        :: "r"((uint32_t)(sdst)), "l"(gsrc), "r"((uint32_t)(bytes)), "r"((uint32_t)(mb)) : "memory")
#define LDS32(r, a) asm volatile("ld.shared.b32 %0, [%1];" : "=r"(r) : "r"(a))
#define MMA16816(d, av, bv) \
    asm volatile("mma.sync.aligned.m16n8k16.row.col.f32.f16.f16.f32 " \
        "{%0,%1,%2,%3}, {%4,%5,%6,%7}, {%8,%9}, {%0,%1,%2,%3};" \
        : "+f"((d)[0]), "+f"((d)[1]), "+f"((d)[2]), "+f"((d)[3]) \
        : "r"((av)[0]), "r"((av)[1]), "r"((av)[2]), "r"((av)[3]), "r"((bv)[0]), "r"((bv)[1]))

// ---------------------------------------------------------------------------
// XLA/Eigen rational tanh replica (bit-matching jnp.tanh — one weight-bin
// flip injects ~2e-3 rel_err).
// ---------------------------------------------------------------------------
__device__ __forceinline__ float xla_tanh(float x) {
    float ax = fabsf(x);
    if (ax < 0.0004f) return x;
    float xc = fminf(fmaxf(x, -7.90531110763549805f), 7.90531110763549805f);
    float x2 = xc * xc;
    float p = -2.76076847742355e-16f;
    p = fmaf(p, x2, 2.00018790482477e-13f);
    p = fmaf(p, x2, -8.60467152213735e-11f);
    p = fmaf(p, x2, 5.12229709037114e-08f);
    p = fmaf(p, x2, 1.48572235717979e-05f);
    p = fmaf(p, x2, 6.37261928875436e-04f);
    p = fmaf(p, x2, 4.89352455891786e-03f);
    p = p * xc;
    float q = 1.19825839466702e-06f;
    q = fmaf(q, x2, 1.18534705686654e-04f);
    q = fmaf(q, x2, 2.26843463243900e-03f);
    q = fmaf(q, x2, 4.89352518554385e-03f);
    return p / q;
}

// ---------------- prep kernels --------------------------------------------
__global__ void k_init(const float* __restrict__ gamma, const float* __restrict__ beta,
                       const float* __restrict__ mean,  const float* __restrict__ var) {
    int t = threadIdx.x;
    if (t == 0) g_max_bits = 0;
    float inv = gamma[t] / sqrtf(var[t] + 1e-5f);
    g_inv[t]  = inv;
    g_bias[t] = beta[t] - mean[t] * inv;
}

__global__ void k_max(const float* __restrict__ w) {
    __shared__ float sm[256];
    float m = 0.f;
    for (int i = blockIdx.x * 256 + threadIdx.x; i < NW; i += gridDim.x * 256)
        m = fmaxf(m, fabsf(xla_tanh(w[i])));
    sm[threadIdx.x] = m;
    __syncthreads();
    for (int s = 128; s > 0; s >>= 1) {
        if (threadIdx.x < s) sm[threadIdx.x] = fmaxf(sm[threadIdx.x], sm[threadIdx.x + s]);
        __syncthreads();
    }
    if (threadIdx.x == 0) atomicMax(&g_max_bits, __float_as_int(sm[0]));
}

// wq*15 = 2q-15 (odd int, exact fp16) -> block layout [tap*8+chunk][co][32ci],
// with the 16B-unit xor (u ^= co&3) baked in so a linear bulk copy lands
// bank-friendly in smem.
__global__ void k_quant16(const float* __restrict__ w) {
    int i = blockIdx.x * blockDim.x + threadIdx.x;
    if (i >= NW) return;
    float M = __int_as_float(g_max_bits);
    float t = xla_tanh(w[i]);
    t = t / (2.0f * M) + 0.5f;
    float q = rintf(t * 15.0f);
    int co = i / 2304;
    int r  = i % 2304;
    int ci = r / 9, tap = r % 9;
    int chunk = ci >> 5, cil = ci & 31, u = cil >> 3;
    int pos = (tap * 8 + chunk) * 8192 + co * 32 + ((u ^ (co & 3)) << 3) + (cil & 7);
    g_w15[pos] = __float2half(2.0f * q - 15.0f);
}

// split x into hi/lo fp16 planes, transposed to [n][pix][ci]
__global__ __launch_bounds__(256) void k_split(const float* __restrict__ x) {
    __shared__ float s[256][33];
    int n = blockIdx.y, px0 = blockIdx.x * 32, t = threadIdx.x;
    const float4* src = (const float4*)(x + ((size_t)(n * 256 + t)) * 3136 + px0);
#pragma unroll
    for (int i = 0; i < 8; i++) {
        float4 v = src[i];
        s[t][i*4+0] = v.x; s[t][i*4+1] = v.y; s[t][i*4+2] = v.z; s[t][i*4+3] = v.w;
    }
    __syncthreads();
    int pl = t >> 3;
    int c0 = (t & 7) * 32;
    uint32_t hbuf[16], lbuf[16];
#pragma unroll
    for (int c = 0; c < 32; c += 2) {
        float f0 = s[c0 + c][pl], f1 = s[c0 + c + 1][pl];
        __half h0 = __float2half(f0), h1 = __float2half(f1);
        __half l0 = __float2half(f0 - __half2float(h0));
        __half l1 = __float2half(f1 - __half2float(h1));
        hbuf[c >> 1] = (uint32_t)__half_as_ushort(h0) | ((uint32_t)__half_as_ushort(h1) << 16);
        lbuf[c >> 1] = (uint32_t)__half_as_ushort(l0) | ((uint32_t)__half_as_ushort(l1) << 16);
    }
    size_t o = ((size_t)(n * 3136 + px0 + pl)) * 256 + c0;
    uint4* dh = (uint4*)(g_xh + o);
    uint4* dl = (uint4*)(g_xl + o);
#pragma unroll
    for (int i = 0; i < 4; i++) {
        dh[i] = make_uint4(hbuf[i*4], hbuf[i*4+1], hbuf[i*4+2], hbuf[i*4+3]);
        dl[i] = make_uint4(lbuf[i*4], lbuf[i*4+1], lbuf[i*4+2], lbuf[i*4+3]);
    }
}

// ---------------------------------------------------------------------------
// Main conv kernel: implicit GEMM via mma.sync (HMMA), split-fp16 exact.
// CTA: M=128 pixels (2 rows x 64), N=256 co, 16 warps (warp tile 32x64).
// 72 stages = 9 taps x 8 ci-chunks(32): A (2 planes) cp.async + zfill halo,
// B one cp.async.bulk (contiguous, pre-swizzled). Double buffered.
// ---------------------------------------------------------------------------
#define A_BYTES   20480               // 2 planes * 128 rows * 80B pitch
#define B_BYTES   16384               // 256 co * 64B
#define BUF_BYTES 36864
#define SMEM_BUF0 3072
#define DSMEM     (SMEM_BUF0 + 2*BUF_BYTES)

__global__ __launch_bounds__(512)
void k_conv(const float* __restrict__ alpha, float* __restrict__ out) {
    extern __shared__ char smem[];
    const uint32_t sb = smem_u32(smem);
    const int t = threadIdx.x;
    const int lane = t & 31, wid = t >> 5;
    const int n = blockIdx.y, h0 = blockIdx.x * 2;

    float* sInv  = (float*)(smem);
    float* sBias = (float*)(smem + 1024);
    const uint32_t mb0 = sb + 2048, mb1 = sb + 2056;

    if (t < 256) { sInv[t] = g_inv[t]; sBias[t] = g_bias[t]; }
    if (t == 0) { MBARRIER_INIT(mb0, 1); MBARRIER_INIT(mb1, 1); }
    __syncthreads();

    const int m0 = (wid & 3) * 32;        // warp M offset (pixels)
    const int n0 = (wid >> 2) * 64;       // warp N offset (co)
    const int g  = lane >> 2;             // fragment row group 0..7
    const int tq = lane & 3;              // fragment quad col 0..3

    float acc[2][8][4];
#pragma unroll
    for (int a1 = 0; a1 < 2; a1++)
#pragma unroll
        for (int a2 = 0; a2 < 8; a2++)
#pragma unroll
            for (int a3 = 0; a3 < 4; a3++) acc[a1][a2][a3] = 0.f;

    const __half* gxp[2] = { g_xh, g_xl };

    // ---- stage loader ----
    auto load_stage = [&](int s) {
        const int buf = s & 1;
        const int tap = s >> 3, chunk = s & 7;
        const int kh = tap / 3, kw = tap % 3, ci0 = chunk * 32;
        const uint32_t aBase = sb + SMEM_BUF0 + buf * BUF_BYTES;
#pragma unroll
        for (int j = 0; j < 2; j++) {
            int i = t + j * 512;               // 0..1023
            int u = i & 3, r = (i >> 2) & 127, pl = i >> 9;
            int hh = h0 + (r >> 6), ww = r & 63;
            int h2 = hh + kh - 1, w2 = ww + kw - 1;
            bool valid = ((unsigned)h2 < 56u) && ((unsigned)w2 < 56u);
            size_t o = valid ? (((size_t)(n * 3136 + h2 * 56 + w2)) * 256 + ci0 + u * 8) : 0;
            const __half* gsrc = gxp[pl] + o;
            uint32_t sdst = aBase + pl * 10240 + r * 80 + u * 16;
            CP_ASYNC16Z(sdst, gsrc, valid ? 16u : 0u);
        }
        CP_ASYNC_COMMIT();
        if (t == 0) {
            uint32_t mb = buf ? mb1 : mb0;
            MBARRIER_EXPECT_TX(mb, B_BYTES);
            CP_BULK(aBase + A_BYTES, (const void*)(g_w15 + (size_t)s * 8192), B_BYTES, mb);
        }
    };

    load_stage(0);

    for (int s = 0; s < 72; s++) {
        const int buf = s & 1;
        if (s + 1 < 72) { load_stage(s + 1); CP_ASYNC_WAIT1(); }
        else            { CP_ASYNC_WAIT0(); }
        MBARRIER_WAIT_PARITY(buf ? mb1 : mb0, (s >> 1) & 1);
        __syncthreads();

        const uint32_t aBase = sb + SMEM_BUF0 + buf * BUF_BYTES;
        const uint32_t bBase = aBase + A_BYTES;

#pragma unroll
        for (int k16 = 0; k16 < 2; k16++) {
            // B fragments: 8 n8-tiles x 2 regs (reused across both planes)
            uint32_t bf[8][2];
#pragma unroll
            for (int nt = 0; nt < 8; nt++) {
                int nl = n0 + nt * 8 + g;
                uint32_t brow = bBase + nl * 64 + 4 * tq;
                int sw = nl & 3;
                LDS32(bf[nt][0], brow + (((k16 * 2 + 0) ^ sw) << 4));
                LDS32(bf[nt][1], brow + (((k16 * 2 + 1) ^ sw) << 4));
            }
#pragma unroll
            for (int pl = 0; pl < 2; pl++) {
#pragma unroll
                for (int mt = 0; mt < 2; mt++) {
                    uint32_t av[4];
                    uint32_t ab = aBase + pl * 10240 + (m0 + mt * 16 + g) * 80 + k16 * 32 + 4 * tq;
                    LDS32(av[0], ab);
                    LDS32(av[1], ab + 640);        // +8 rows
                    LDS32(av[2], ab + 16);         // k+8
                    LDS32(av[3], ab + 656);
#pragma unroll
                    for (int nt = 0; nt < 8; nt++)
                        MMA16816(acc[mt][nt], av, bf[nt]);
                }
            }
        }
        __syncthreads();
    }

    // ---- epilogue: /15 -> BN -> PACT -> store ----
    const float a = alpha[0];
    const float stepq = a / 15.0f;
#pragma unroll
    for (int mt = 0; mt < 2; mt++) {
#pragma unroll
        for (int nt = 0; nt < 8; nt++) {
#pragma unroll
            for (int e = 0; e < 4; e++) {
                int pix = m0 + mt * 16 + g + (e >> 1) * 8;
                int co  = n0 + nt * 8 + tq * 2 + (e & 1);
                int hh = h0 + (pix >> 6), ww = pix & 63;
                if (ww < 56) {
                    float y = acc[mt][nt][e] * (1.0f / 15.0f);
                    float v = y * sInv[co] + sBias[co];
                    v = fminf(fmaxf(v, 0.f), a);
                    float q = rintf(v * 15.0f / a);
                    out[((size_t)(n * 256 + co)) * 3136 + hh * 56 + ww] = q * stepq;
                }
            }
        }
    }
}

// ---------------------------------------------------------------------------
extern "C" void kernel_launch(void* const* d_in, const int* in_sizes, int n_in,
                              void* d_out, int out_size) {
    const float* x     = (const float*)d_in[0];
    const float* w     = (const float*)d_in[1];
    const float* gamma = (const float*)d_in[2];
    const float* beta  = (const float*)d_in[3];
    const float* mean  = (const float*)d_in[4];
    const float* var   = (const float*)d_in[5];
    const float* alpha = (const float*)d_in[6];
    float* out = (float*)d_out;

    static bool attr_set = false;
    if (!attr_set) {
        cudaFuncSetAttribute(k_conv, cudaFuncAttributeMaxDynamicSharedMemorySize, DSMEM);
        attr_set = true;
    }

    k_init<<<1, 256>>>(gamma, beta, mean, var);
    k_max<<<148, 256>>>(w);
    k_quant16<<<2304, 256>>>(w);
    k_split<<<dim3(98, 32), 256>>>(x);
    k_conv<<<dim3(28, 32), 512, DSMEM>>>(alpha, out);
}

// round 7
// speedup vs baseline: 5.0325x; 1.1887x over previous
#include <cuda_runtime.h>
#include <cuda_fp16.h>
#include <cstdint>

#define NW (256*256*9)

// ---------------- scratch (device globals; no allocation allowed) ----------
__device__ float  g_inv[256];
__device__ float  g_bias[256];
__device__ int    g_max_bits;
// B: 36 stage-blocks of [256 co][72 halfs] (64 ci data + 8 pad) = 36,864B each
__device__ __align__(16) __half g_w15[36*256*72];
__device__ __align__(16) __half g_xh[32*3136*256];    // [n][pix][ci] hi plane
__device__ __align__(16) __half g_xl[32*3136*256];    // [n][pix][ci] lo plane

// ---------------- PTX helpers ---------------------------------------------
__device__ __forceinline__ uint32_t smem_u32(const void* p) {
    uint32_t a;
    asm("{ .reg .u64 t; cvta.to.shared.u64 t, %1; cvt.u32.u64 %0, t; }" : "=r"(a) : "l"(p));
    return a;
}
#define MBARRIER_INIT(mb, c) \
    asm volatile("mbarrier.init.shared.b64 [%0], %1;" :: "r"((uint32_t)(mb)), "r"((uint32_t)(c)) : "memory")
#define MBARRIER_EXPECT_TX(mb, b) \
    asm volatile("mbarrier.arrive.expect_tx.shared.b64 _, [%0], %1;" :: "r"((uint32_t)(mb)), "r"((uint32_t)(b)) : "memory")
#define MBARRIER_WAIT_PARITY(mb, ph) do { \
    uint32_t _m = (uint32_t)(mb), _p = (uint32_t)(ph), _d; \
    asm volatile("{ .reg .pred p; mbarrier.try_wait.parity.acquire.cta.shared::cta.b64 p, [%1], %2; selp.b32 %0,1,0,p; }" \
        : "=r"(_d) : "r"(_m), "r"(_p) : "memory"); \
    if (!_d) { \
        asm volatile("{ .reg .pred P1; WL_%=: mbarrier.try_wait.parity.acquire.cta.shared::cta.b64 P1, [%0], %1, 0x989680; @P1 bra.uni WD_%=; bra.uni WL_%=; WD_%=: }" \
            :: "r"(_m), "r"(_p) : "memory"); \
    } } while (0)
#define CP_ASYNC16Z(sdst, gsrc, sz) \
    asm volatile("cp.async.cg.shared.global [%0], [%1], 16, %2;" :: "r"(sdst), "l"(gsrc), "r"(sz) : "memory")
#define CP_ASYNC_COMMIT() asm volatile("cp.async.commit_group;" ::: "memory")
#define CP_ASYNC_WAIT1()  asm volatile("cp.async.wait_group 1;" ::: "memory")
#define CP_ASYNC_WAIT0()  asm volatile("cp.async.wait_group 0;" ::: "memory")
#define CP_BULK(sdst, gsrc, bytes, mb) \
    asm volatile("cp.async.bulk.shared::cluster.global.mbarrier::complete_tx::bytes [%0], [%1], %2, [%3];" \
        :: "r"((uint32_t)(sdst)), "l"(gsrc), "r"((uint32_t)(bytes)), "r"((uint32_t)(mb)) : "memory")
#define LDSM_X4(r0, r1, r2, r3, a) \
    asm volatile("ldmatrix.sync.aligned.m8n8.x4.shared.b16 {%0,%1,%2,%3}, [%4];" \
        : "=r"(r0), "=r"(r1), "=r"(r2), "=r"(r3) : "r"(a))
#define MMA16816(d, av, bv) \
    asm volatile("mma.sync.aligned.m16n8k16.row.col.f32.f16.f16.f32 " \
        "{%0,%1,%2,%3}, {%4,%5,%6,%7}, {%8,%9}, {%0,%1,%2,%3};" \
        : "+f"((d)[0]), "+f"((d)[1]), "+f"((d)[2]), "+f"((d)[3]) \
        : "r"((av)[0]), "r"((av)[1]), "r"((av)[2]), "r"((av)[3]), "r"((bv)[0]), "r"((bv)[1]))

// ---------------------------------------------------------------------------
// XLA/Eigen rational tanh replica (bit-matching jnp.tanh — one weight-bin
// flip injects ~2e-3 rel_err).
// ---------------------------------------------------------------------------
__device__ __forceinline__ float xla_tanh(float x) {
    float ax = fabsf(x);
    if (ax < 0.0004f) return x;
    float xc = fminf(fmaxf(x, -7.90531110763549805f), 7.90531110763549805f);
    float x2 = xc * xc;
    float p = -2.76076847742355e-16f;
    p = fmaf(p, x2, 2.00018790482477e-13f);
    p = fmaf(p, x2, -8.60467152213735e-11f);
    p = fmaf(p, x2, 5.12229709037114e-08f);
    p = fmaf(p, x2, 1.48572235717979e-05f);
    p = fmaf(p, x2, 6.37261928875436e-04f);
    p = fmaf(p, x2, 4.89352455891786e-03f);
    p = p * xc;
    float q = 1.19825839466702e-06f;
    q = fmaf(q, x2, 1.18534705686654e-04f);
    q = fmaf(q, x2, 2.26843463243900e-03f);
    q = fmaf(q, x2, 4.89352518554385e-03f);
    return p / q;
}

// ---------------- prep kernels --------------------------------------------
__global__ void k_init(const float* __restrict__ gamma, const float* __restrict__ beta,
                       const float* __restrict__ mean,  const float* __restrict__ var) {
    int t = threadIdx.x;
    if (t == 0) g_max_bits = 0;
    float inv = gamma[t] / sqrtf(var[t] + 1e-5f);
    g_inv[t]  = inv;
    g_bias[t] = beta[t] - mean[t] * inv;
}

__global__ void k_max(const float* __restrict__ w) {
    __shared__ float sm[256];
    float m = 0.f;
    for (int i = blockIdx.x * 256 + threadIdx.x; i < NW; i += gridDim.x * 256)
        m = fmaxf(m, fabsf(xla_tanh(w[i])));
    sm[threadIdx.x] = m;
    __syncthreads();
    for (int s = 128; s > 0; s >>= 1) {
        if (threadIdx.x < s) sm[threadIdx.x] = fmaxf(sm[threadIdx.x], sm[threadIdx.x + s]);
        __syncthreads();
    }
    if (threadIdx.x == 0) atomicMax(&g_max_bits, __float_as_int(sm[0]));
}

// wq*15 = 2q-15 (odd int, exact fp16) -> stage blocks [tap*4+chunk][co][72]
__global__ void k_quant16(const float* __restrict__ w) {
    int i = blockIdx.x * blockDim.x + threadIdx.x;
    if (i >= NW) return;
    float M = __int_as_float(g_max_bits);
    float t = xla_tanh(w[i]);
    t = t / (2.0f * M) + 0.5f;
    float q = rintf(t * 15.0f);
    int co = i / 2304;
    int r  = i % 2304;
    int ci = r / 9, tap = r % 9;
    int s = tap * 4 + (ci >> 6);
    g_w15[(size_t)s * 18432 + co * 72 + (ci & 63)] = __float2half(2.0f * q - 15.0f);
}

// split x into hi/lo fp16 planes, transposed to [n][pix][ci]
__global__ __launch_bounds__(256) void k_split(const float* __restrict__ x) {
    __shared__ float s[256][33];
    int n = blockIdx.y, px0 = blockIdx.x * 32, t = threadIdx.x;
    const float4* src = (const float4*)(x + ((size_t)(n * 256 + t)) * 3136 + px0);
#pragma unroll
    for (int i = 0; i < 8; i++) {
        float4 v = src[i];
        s[t][i*4+0] = v.x; s[t][i*4+1] = v.y; s[t][i*4+2] = v.z; s[t][i*4+3] = v.w;
    }
    __syncthreads();
    const int pl = t >> 3;               // pixel 0..31
    const int c0 = (t & 7) * 4;          // ci stride-4 group -> conflict-free reads
    __half* dh = g_xh + ((size_t)(n * 3136 + px0 + pl)) * 256;
    __half* dl = g_xl + ((size_t)(n * 3136 + px0 + pl)) * 256;
#pragma unroll
    for (int j = 0; j < 8; j++) {
        int cb = j * 32 + c0;
        uint32_t hb[2], lb[2];
#pragma unroll
        for (int c = 0; c < 4; c += 2) {
            float f0 = s[cb + c][pl], f1 = s[cb + c + 1][pl];
            __half h0 = __float2half(f0), h1 = __float2half(f1);
            __half l0 = __float2half(f0 - __half2float(h0));
            __half l1 = __float2half(f1 - __half2float(h1));
            hb[c >> 1] = (uint32_t)__half_as_ushort(h0) | ((uint32_t)__half_as_ushort(h1) << 16);
            lb[c >> 1] = (uint32_t)__half_as_ushort(l0) | ((uint32_t)__half_as_ushort(l1) << 16);
        }
        *(uint2*)(dh + cb) = make_uint2(hb[0], hb[1]);
        *(uint2*)(dl + cb) = make_uint2(lb[0], lb[1]);
    }
}

// ---------------------------------------------------------------------------
// Main conv kernel: implicit GEMM via mma.sync + ldmatrix, split-fp16 exact.
// CTA: M=128 pixels (2 rows x 64), N=256 co, 16 warps (warp tile 32x64).
// 36 stages = 9 taps x 4 ci-chunks(64). A: cp.async + zfill halo (144B pitch);
// B: one cp.async.bulk per stage (contiguous [co][72] block). Double buffered.
// ---------------------------------------------------------------------------
#define A_PLANE  18432                 // 128 rows * 144B
#define A_BYTES  (2*A_PLANE)           // 36864
#define B_BYTES  36864                 // 256 co * 144B (incl pad)
#define BUF_BYTES (A_BYTES + B_BYTES)  // 73728
#define SMEM_BUF0 3072
#define DSMEM     (SMEM_BUF0 + 2*BUF_BYTES)

__global__ __launch_bounds__(512)
void k_conv(const float* __restrict__ alpha, float* __restrict__ out) {
    extern __shared__ char smem[];
    const uint32_t sb = smem_u32(smem);
    const int t = threadIdx.x;
    const int lane = t & 31, wid = t >> 5;
    const int n = blockIdx.y, h0 = blockIdx.x * 2;

    float* sInv  = (float*)(smem);
    float* sBias = (float*)(smem + 1024);
    const uint32_t mb0 = sb + 2048, mb1 = sb + 2056;

    if (t < 256) { sInv[t] = g_inv[t]; sBias[t] = g_bias[t]; }
    if (t == 0) { MBARRIER_INIT(mb0, 1); MBARRIER_INIT(mb1, 1); }
    __syncthreads();

    const int m0 = (wid & 3) * 32;        // warp M offset (pixels)
    const int n0 = (wid >> 2) * 64;       // warp N offset (co)
    const int g  = lane >> 2;             // fragment row group 0..7
    const int tq = lane & 3;              // fragment quad col 0..3
    const int l7 = lane & 7, lq = lane >> 3;  // ldmatrix addressing

    float acc[2][8][4];
#pragma unroll
    for (int a1 = 0; a1 < 2; a1++)
#pragma unroll
        for (int a2 = 0; a2 < 8; a2++)
#pragma unroll
            for (int a3 = 0; a3 < 4; a3++) acc[a1][a2][a3] = 0.f;

    const __half* gxp[2] = { g_xh, g_xl };

    // ---- stage loader ----
    auto load_stage = [&](int s) {
        const int buf = s & 1;
        const int tap = s >> 2, chunk = s & 3;
        const int kh = tap / 3, kw = tap % 3, ci0 = chunk * 64;
        const uint32_t aBase = sb + SMEM_BUF0 + buf * BUF_BYTES;
#pragma unroll
        for (int j = 0; j < 4; j++) {
            int i = t + j * 512;               // 0..2047
            int u = i & 7, r = (i >> 3) & 127, pl = i >> 10;
            int hh = h0 + (r >> 6), ww = r & 63;
            int h2 = hh + kh - 1, w2 = ww + kw - 1;
            bool valid = ((unsigned)h2 < 56u) && ((unsigned)w2 < 56u);
            size_t o = valid ? (((size_t)(n * 3136 + h2 * 56 + w2)) * 256 + ci0 + u * 8) : 0;
            const __half* gsrc = gxp[pl] + o;
            uint32_t sdst = aBase + pl * A_PLANE + r * 144 + u * 16;
            CP_ASYNC16Z(sdst, gsrc, valid ? 16u : 0u);
        }
        CP_ASYNC_COMMIT();
        if (t == 0) {
            uint32_t mb = buf ? mb1 : mb0;
            MBARRIER_EXPECT_TX(mb, B_BYTES);
            CP_BULK(aBase + A_BYTES, (const void*)(g_w15 + (size_t)s * 18432), B_BYTES, mb);
        }
    };

    load_stage(0);

    for (int s = 0; s < 36; s++) {
        const int buf = s & 1;
        if (s + 1 < 36) { load_stage(s + 1); CP_ASYNC_WAIT1(); }
        else            { CP_ASYNC_WAIT0(); }
        MBARRIER_WAIT_PARITY(buf ? mb1 : mb0, (s >> 1) & 1);
        __syncthreads();

        const uint32_t aBase = sb + SMEM_BUF0 + buf * BUF_BYTES;
        const uint32_t bBase = aBase + A_BYTES;

#pragma unroll
        for (int k16 = 0; k16 < 4; k16++) {
            // B fragments: 8 n8-tiles x 2 regs via 4 ldmatrix.x4
            uint32_t bf[8][2];
#pragma unroll
            for (int ntp = 0; ntp < 4; ntp++) {
                uint32_t ba = bBase + (uint32_t)(n0 + ntp * 16 + l7 + (lq >> 1) * 8) * 144
                            + k16 * 32 + (lq & 1) * 16;
                LDSM_X4(bf[2*ntp][0], bf[2*ntp][1], bf[2*ntp+1][0], bf[2*ntp+1][1], ba);
            }
#pragma unroll
            for (int pl = 0; pl < 2; pl++) {
#pragma unroll
                for (int mt = 0; mt < 2; mt++) {
                    uint32_t av[4];
                    uint32_t aa = aBase + pl * A_PLANE
                                + (uint32_t)(m0 + mt * 16 + l7 + (lq & 1) * 8) * 144
                                + k16 * 32 + (lq >> 1) * 16;
                    LDSM_X4(av[0], av[1], av[2], av[3], aa);
#pragma unroll
                    for (int nt = 0; nt < 8; nt++)
                        MMA16816(acc[mt][nt], av, bf[nt]);
                }
            }
        }
        __syncthreads();
    }

    // ---- epilogue: /15 -> BN -> PACT -> store ----
    const float a = alpha[0];
    const float stepq = a / 15.0f;
#pragma unroll
    for (int mt = 0; mt < 2; mt++) {
#pragma unroll
        for (int nt = 0; nt < 8; nt++) {
#pragma unroll
            for (int e = 0; e < 4; e++) {
                int pix = m0 + mt * 16 + g + (e >> 1) * 8;
                int co  = n0 + nt * 8 + tq * 2 + (e & 1);
                int hh = h0 + (pix >> 6), ww = pix & 63;
                if (ww < 56) {
                    float y = acc[mt][nt][e] * (1.0f / 15.0f);
                    float v = y * sInv[co] + sBias[co];
                    v = fminf(fmaxf(v, 0.f), a);
                    float q = rintf(v * 15.0f / a);
                    out[((size_t)(n * 256 + co)) * 3136 + hh * 56 + ww] = q * stepq;
                }
            }
        }
    }
}

// ---------------------------------------------------------------------------
extern "C" void kernel_launch(void* const* d_in, const int* in_sizes, int n_in,
                              void* d_out, int out_size) {
    const float* x     = (const float*)d_in[0];
    const float* w     = (const float*)d_in[1];
    const float* gamma = (const float*)d_in[2];
    const float* beta  = (const float*)d_in[3];
    const float* mean  = (const float*)d_in[4];
    const float* var   = (const float*)d_in[5];
    const float* alpha = (const float*)d_in[6];
    float* out = (float*)d_out;

    static bool attr_set = false;
    if (!attr_set) {
        cudaFuncSetAttribute(k_conv, cudaFuncAttributeMaxDynamicSharedMemorySize, DSMEM);
        attr_set = true;
    }

    k_init<<<1, 256>>>(gamma, beta, mean, var);
    k_max<<<148, 256>>>(w);
    k_quant16<<<2304, 256>>>(w);
    k_split<<<dim3(98, 32), 256>>>(x);
    k_conv<<<dim3(28, 32), 512, DSMEM>>>(alpha, out);
}

// round 9
// speedup vs baseline: 5.8496x; 1.1624x over previous
#include <cuda_runtime.h>
#include <cuda_fp16.h>
#include <cstdint>

#define NW (256*256*9)

// ---------------- scratch (device globals; no allocation allowed) ----------
__device__ float  g_inv[256];
__device__ float  g_bias[256];
__device__ int    g_max_bits;
// B: 36 blocks [chunk*9+tap][256 co][64 halfs], 16B-unit xor (co&7) baked in
__device__ __align__(16) __half g_w15[36*256*64];
__device__ __align__(16) __half g_xh[32*3136*256];    // [n][pix][ci] hi plane
__device__ __align__(16) __half g_xl[32*3136*256];    // [n][pix][ci] lo plane

// ---------------- PTX helpers ---------------------------------------------
__device__ __forceinline__ uint32_t smem_u32(const void* p) {
    uint32_t a;
    asm("{ .reg .u64 t; cvta.to.shared.u64 t, %1; cvt.u32.u64 %0, t; }" : "=r"(a) : "l"(p));
    return a;
}
#define MBARRIER_INIT(mb, c) \
    asm volatile("mbarrier.init.shared.b64 [%0], %1;" :: "r"((uint32_t)(mb)), "r"((uint32_t)(c)) : "memory")
#define MBARRIER_EXPECT_TX(mb, b) \
    asm volatile("mbarrier.arrive.expect_tx.shared.b64 _, [%0], %1;" :: "r"((uint32_t)(mb)), "r"((uint32_t)(b)) : "memory")
#define MBARRIER_WAIT_PARITY(mb, ph) do { \
    uint32_t _m = (uint32_t)(mb), _p = (uint32_t)(ph), _d; \
    asm volatile("{ .reg .pred p; mbarrier.try_wait.parity.acquire.cta.shared::cta.b64 p, [%1], %2; selp.b32 %0,1,0,p; }" \
        : "=r"(_d) : "r"(_m), "r"(_p) : "memory"); \
    if (!_d) { \
        asm volatile("{ .reg .pred P1; WL_%=: mbarrier.try_wait.parity.acquire.cta.shared::cta.b64 P1, [%0], %1, 0x989680; @P1 bra.uni WD_%=; bra.uni WL_%=; WD_%=: }" \
            :: "r"(_m), "r"(_p) : "memory"); \
    } } while (0)
#define CP_ASYNC16Z(sdst, gsrc, sz) \
    asm volatile("cp.async.cg.shared.global [%0], [%1], 16, %2;" :: "r"(sdst), "l"(gsrc), "r"(sz) : "memory")
#define CP_ASYNC_COMMIT() asm volatile("cp.async.commit_group;" ::: "memory")
#define CP_ASYNC_WAIT1()  asm volatile("cp.async.wait_group 1;" ::: "memory")
#define CP_ASYNC_WAIT0()  asm volatile("cp.async.wait_group 0;" ::: "memory")
#define CP_BULK(sdst, gsrc, bytes, mb) \
    asm volatile("cp.async.bulk.shared::cluster.global.mbarrier::complete_tx::bytes [%0], [%1], %2, [%3];" \
        :: "r"((uint32_t)(sdst)), "l"(gsrc), "r"((uint32_t)(bytes)), "r"((uint32_t)(mb)) : "memory")
#define LDSM_X4(r0, r1, r2, r3, a) \
    asm volatile("ldmatrix.sync.aligned.m8n8.x4.shared.b16 {%0,%1,%2,%3}, [%4];" \
        : "=r"(r0), "=r"(r1), "=r"(r2), "=r"(r3) : "r"(a))
#define MMA16816(d, av, bv) \
    asm volatile("mma.sync.aligned.m16n8k16.row.col.f32.f16.f16.f32 " \
        "{%0,%1,%2,%3}, {%4,%5,%6,%7}, {%8,%9}, {%0,%1,%2,%3};" \
        : "+f"((d)[0]), "+f"((d)[1]), "+f"((d)[2]), "+f"((d)[3]) \
        : "r"((av)[0]), "r"((av)[1]), "r"((av)[2]), "r"((av)[3]), "r"((bv)[0]), "r"((bv)[1]))

// ---------------------------------------------------------------------------
// XLA/Eigen rational tanh replica (bit-matching jnp.tanh — one weight-bin
// flip injects ~2e-3 rel_err).
// ---------------------------------------------------------------------------
__device__ __forceinline__ float xla_tanh(float x) {
    float ax = fabsf(x);
    if (ax < 0.0004f) return x;
    float xc = fminf(fmaxf(x, -7.90531110763549805f), 7.90531110763549805f);
    float x2 = xc * xc;
    float p = -2.76076847742355e-16f;
    p = fmaf(p, x2, 2.00018790482477e-13f);
    p = fmaf(p, x2, -8.60467152213735e-11f);
    p = fmaf(p, x2, 5.12229709037114e-08f);
    p = fmaf(p, x2, 1.48572235717979e-05f);
    p = fmaf(p, x2, 6.37261928875436e-04f);
    p = fmaf(p, x2, 4.89352455891786e-03f);
    p = p * xc;
    float q = 1.19825839466702e-06f;
    q = fmaf(q, x2, 1.18534705686654e-04f);
    q = fmaf(q, x2, 2.26843463243900e-03f);
    q = fmaf(q, x2, 4.89352518554385e-03f);
    return p / q;
}

// ---------------- prep kernels --------------------------------------------
__global__ void k_init(const float* __restrict__ gamma, const float* __restrict__ beta,
                       const float* __restrict__ mean,  const float* __restrict__ var) {
    int t = threadIdx.x;
    if (t == 0) g_max_bits = 0;
    float inv = gamma[t] / sqrtf(var[t] + 1e-5f);
    g_inv[t]  = inv;
    g_bias[t] = beta[t] - mean[t] * inv;
}

__global__ void k_max(const float* __restrict__ w) {
    __shared__ float sm[256];
    float m = 0.f;
    for (int i = blockIdx.x * 256 + threadIdx.x; i < NW; i += gridDim.x * 256)
        m = fmaxf(m, fabsf(xla_tanh(w[i])));
    sm[threadIdx.x] = m;
    __syncthreads();
    for (int s = 128; s > 0; s >>= 1) {
        if (threadIdx.x < s) sm[threadIdx.x] = fmaxf(sm[threadIdx.x], sm[threadIdx.x + s]);
        __syncthreads();
    }
    if (threadIdx.x == 0) atomicMax(&g_max_bits, __float_as_int(sm[0]));
}

// wq*15 = 2q-15 (odd int, exact fp16) -> blocks [(ci>>6)*9+tap][co][64],
// 16B-unit xor(co&7) baked so a linear bulk copy lands ldmatrix-conflict-free.
__global__ void k_quant16(const float* __restrict__ w) {
    int i = blockIdx.x * blockDim.x + threadIdx.x;
    if (i >= NW) return;
    float M = __int_as_float(g_max_bits);
    float t = xla_tanh(w[i]);
    t = t / (2.0f * M) + 0.5f;
    float q = rintf(t * 15.0f);
    int co = i / 2304;
    int r  = i % 2304;
    int ci = r / 9, tap = r % 9;
    int s  = (ci >> 6) * 9 + tap;
    int u0 = (ci & 63) >> 3;
    int pos = s * 16384 + co * 64 + ((u0 ^ (co & 7)) << 3) + (ci & 7);
    g_w15[pos] = __float2half(2.0f * q - 15.0f);
}

// split x into hi/lo fp16 planes, transposed to [n][pix][ci]
__global__ __launch_bounds__(256) void k_split(const float* __restrict__ x) {
    __shared__ float s[256][33];
    int n = blockIdx.y, px0 = blockIdx.x * 32, t = threadIdx.x;
    const float4* src = (const float4*)(x + ((size_t)(n * 256 + t)) * 3136 + px0);
#pragma unroll
    for (int i = 0; i < 8; i++) {
        float4 v = src[i];
        s[t][i*4+0] = v.x; s[t][i*4+1] = v.y; s[t][i*4+2] = v.z; s[t][i*4+3] = v.w;
    }
    __syncthreads();
    const int pl = t >> 3;
    const int c0 = (t & 7) * 4;
    __half* dh = g_xh + ((size_t)(n * 3136 + px0 + pl)) * 256;
    __half* dl = g_xl + ((size_t)(n * 3136 + px0 + pl)) * 256;
#pragma unroll
    for (int j = 0; j < 8; j++) {
        int cb = j * 32 + c0;
        uint32_t hb[2], lb[2];
#pragma unroll
        for (int c = 0; c < 4; c += 2) {
            float f0 = s[cb + c][pl], f1 = s[cb + c + 1][pl];
            __half h0 = __float2half(f0), h1 = __float2half(f1);
            __half l0 = __float2half(f0 - __half2float(h0));
            __half l1 = __float2half(f1 - __half2float(h1));
            hb[c >> 1] = (uint32_t)__half_as_ushort(h0) | ((uint32_t)__half_as_ushort(h1) << 16);
            lb[c >> 1] = (uint32_t)__half_as_ushort(l0) | ((uint32_t)__half_as_ushort(l1) << 16);
        }
        *(uint2*)(dh + cb) = make_uint2(hb[0], hb[1]);
        *(uint2*)(dl + cb) = make_uint2(lb[0], lb[1]);
    }
}

// ---------------------------------------------------------------------------
// Main conv kernel: implicit GEMM, split-fp16 exact, TAP-REUSE A patches.
// CTA: M=128 pixels (2 rows x full 64-col width), N=256 co, 16 warps.
// 4 chunk-stages (64 ci each): one halo patch (2 planes x 4h x 66w x 64ci)
// loaded per chunk via cp.async (double-buffered); 9 taps read shifted views
// via per-lane ldmatrix addresses. B: per-tap cp.async.bulk (double-buffered).
// ---------------------------------------------------------------------------
#define A_PLANE  33792                 // 264 pix * 128B
#define A_BUF    (2*A_PLANE)           // 67584 (both planes)
#define B_BUF    32768                 // 256 co * 128B
#define SMEM_BUF0 3072
#define DSMEM    (SMEM_BUF0 + 2*A_BUF + 2*B_BUF)   // 203776

__global__ __launch_bounds__(512)
void k_conv(const float* __restrict__ alpha, float* __restrict__ out) {
    extern __shared__ char smem[];
    const uint32_t sb = smem_u32(smem);
    const int t = threadIdx.x;
    const int lane = t & 31, wid = t >> 5;
    const int n = blockIdx.y, h0 = blockIdx.x * 2;

    float* sInv  = (float*)(smem);
    float* sBias = (float*)(smem + 1024);
    const uint32_t mbA[2] = { sb + 2048, sb + 2056 };

    if (t < 256) { sInv[t] = g_inv[t]; sBias[t] = g_bias[t]; }
    if (t == 0) { MBARRIER_INIT(mbA[0], 1); MBARRIER_INIT(mbA[1], 1); }
    __syncthreads();

    const int m0 = (wid & 3) * 32;
    const int n0 = (wid >> 2) * 64;
    const int g  = lane >> 2;
    const int tq = lane & 3;
    const int l7 = lane & 7, lq = lane >> 3;

    // A fragment base pixel (within patch coords, before tap shift)
    int baseP[2];
#pragma unroll
    for (int mt = 0; mt < 2; mt++) {
        int mr = m0 + mt * 16 + l7 + (lq & 1) * 8;
        baseP[mt] = (mr >> 6) * 66 + (mr & 63);
    }
    // B fragment row bases
    uint32_t coB[4], coX[4];
#pragma unroll
    for (int ntp = 0; ntp < 4; ntp++) {
        int co = n0 + ntp * 16 + l7 + (lq >> 1) * 8;
        coB[ntp] = (uint32_t)co << 7;
        coX[ntp] = (uint32_t)(co & 7);
    }

    float acc[2][8][4];
#pragma unroll
    for (int a1 = 0; a1 < 2; a1++)
#pragma unroll
        for (int a2 = 0; a2 < 8; a2++)
#pragma unroll
            for (int a3 = 0; a3 < 4; a3++) acc[a1][a2][a3] = 0.f;

    const __half* gxp[2] = { g_xh, g_xl };

    // ---- A patch loader: chunk cn -> buf cn&1 ----
    auto load_A = [&](int cn) {
        const int ci0 = cn * 64;
        const uint32_t aBase = sb + SMEM_BUF0 + (cn & 1) * A_BUF;
#pragma unroll
        for (int j = 0; j < 9; j++) {
            int i = t + j * 512;
            if (i < 4224) {
                int u = i & 7, idx8 = i >> 3;
                int pl = (idx8 >= 264) ? 1 : 0;
                int p  = idx8 - pl * 264;
                int hr = p / 66, wc = p - hr * 66;
                int h2 = h0 - 1 + hr, w2 = wc - 1;
                bool valid = ((unsigned)h2 < 56u) && ((unsigned)w2 < 56u);
                size_t o = valid ? (((size_t)(n * 3136 + h2 * 56 + w2)) * 256 + ci0 + u * 8) : 0;
                uint32_t sdst = aBase + pl * A_PLANE + (p << 7) + (((u ^ (p & 7))) << 4);
                CP_ASYNC16Z(sdst, gxp[pl] + o, valid ? 16u : 0u);
            }
        }
        CP_ASYNC_COMMIT();
    };

    // prologue: B block 0 prefetch + A chunk 0
    if (t == 0) {
        MBARRIER_EXPECT_TX(mbA[0], B_BUF);
        CP_BULK(sb + SMEM_BUF0 + 2 * A_BUF, (const void*)g_w15, B_BUF, mbA[0]);
    }
    load_A(0);

    for (int c = 0; c < 4; c++) {
        __syncthreads();                       // all reads of A[c-1] done
        if (c < 3) { load_A(c + 1); CP_ASYNC_WAIT1(); }
        else       { CP_ASYNC_WAIT0(); }
        const uint32_t aBase = sb + SMEM_BUF0 + (c & 1) * A_BUF;

        for (int tap = 0; tap < 9; tap++) {
            const int idx = c * 9 + tap;
            __syncthreads();                   // B[idx-1] reads done; A[c] visible
            if (t == 0 && idx < 35) {
                uint32_t mb = mbA[(idx + 1) & 1];
                MBARRIER_EXPECT_TX(mb, B_BUF);
                CP_BULK(sb + SMEM_BUF0 + 2 * A_BUF + ((idx + 1) & 1) * B_BUF,
                        (const void*)(g_w15 + (size_t)(idx + 1) * 16384), B_BUF, mb);
            }
            MBARRIER_WAIT_PARITY(mbA[idx & 1], (idx >> 1) & 1);

            const uint32_t bBase = sb + SMEM_BUF0 + 2 * A_BUF + (idx & 1) * B_BUF;
            const int kh = tap / 3, kw = tap - kh * 3;
            const int tapAdd = kh * 66 + kw;

#pragma unroll
            for (int k16 = 0; k16 < 4; k16++) {
                uint32_t bf[8][2];
#pragma unroll
                for (int ntp = 0; ntp < 4; ntp++) {
                    uint32_t ba = bBase + coB[ntp]
                                + ((((uint32_t)(k16 * 2) + (lq & 1)) ^ coX[ntp]) << 4);
                    LDSM_X4(bf[2*ntp][0], bf[2*ntp][1], bf[2*ntp+1][0], bf[2*ntp+1][1], ba);
                }
#pragma unroll
                for (int pl = 0; pl < 2; pl++) {
#pragma unroll
                    for (int mt = 0; mt < 2; mt++) {
                        int p = baseP[mt] + tapAdd;
                        uint32_t aa = aBase + pl * A_PLANE + ((uint32_t)p << 7)
                                    + ((((uint32_t)(k16 * 2) + (lq >> 1)) ^ (uint32_t)(p & 7)) << 4);
                        uint32_t av[4];
                        LDSM_X4(av[0], av[1], av[2], av[3], aa);
#pragma unroll
                        for (int nt = 0; nt < 8; nt++)
                            MMA16816(acc[mt][nt], av, bf[nt]);
                    }
                }
            }
        }
    }

    // ---- epilogue: /15 -> BN -> PACT -> store ----
    const float a = alpha[0];
    const float stepq = a / 15.0f;
#pragma unroll
    for (int mt = 0; mt < 2; mt++) {
#pragma unroll
        for (int nt = 0; nt < 8; nt++) {
#pragma unroll
            for (int e = 0; e < 4; e++) {
                int pix = m0 + mt * 16 + g + (e >> 1) * 8;
                int co  = n0 + nt * 8 + tq * 2 + (e & 1);
                int hh = h0 + (pix >> 6), ww = pix & 63;
                if (ww < 56) {
                    float y = acc[mt][nt][e] * (1.0f / 15.0f);
                    float v = y * sInv[co] + sBias[co];
                    v = fminf(fmaxf(v, 0.f), a);
                    float q = rintf(v * 15.0f / a);
                    out[((size_t)(n * 256 + co)) * 3136 + hh * 56 + ww] = q * stepq;
                }
            }
        }
    }
}

// ---------------------------------------------------------------------------
extern "C" void kernel_launch(void* const* d_in, const int* in_sizes, int n_in,
                              void* d_out, int out_size) {
    const float* x     = (const float*)d_in[0];
    const float* w     = (const float*)d_in[1];
    const float* gamma = (const float*)d_in[2];
    const float* beta  = (const float*)d_in[3];
    const float* mean  = (const float*)d_in[4];
    const float* var   = (const float*)d_in[5];
    const float* alpha = (const float*)d_in[6];
    float* out = (float*)d_out;

    static bool attr_set = false;
    if (!attr_set) {
        cudaFuncSetAttribute(k_conv, cudaFuncAttributeMaxDynamicSharedMemorySize, DSMEM);
        attr_set = true;
    }

    k_init<<<1, 256>>>(gamma, beta, mean, var);
    k_max<<<148, 256>>>(w);
    k_quant16<<<2304, 256>>>(w);
    k_split<<<dim3(98, 32), 256>>>(x);
    k_conv<<<dim3(28, 32), 512, DSMEM>>>(alpha, out);
}

// round 10
// speedup vs baseline: 6.6485x; 1.1366x over previous
#include <cuda_runtime.h>
#include <cuda_fp16.h>
#include <cstdint>

#define NW (256*256*9)

// ---------------- scratch (device globals; no allocation allowed) ----------
__device__ float  g_inv[256];
__device__ float  g_bias[256];
__device__ int    g_max_bits;
// B: 36 blocks [chunk*9+tap][256 co][64 halfs], 16B-unit xor (co&7) baked in
__device__ __align__(16) __half g_w15[36*256*64];
__device__ __align__(16) __half g_xh[32*3136*256];    // [n][pix][ci] hi plane
__device__ __align__(16) __half g_xl[32*3136*256];    // [n][pix][ci] lo plane

// ---------------- PTX helpers ---------------------------------------------
__device__ __forceinline__ uint32_t smem_u32(const void* p) {
    uint32_t a;
    asm("{ .reg .u64 t; cvta.to.shared.u64 t, %1; cvt.u32.u64 %0, t; }" : "=r"(a) : "l"(p));
    return a;
}
#define MBARRIER_INIT(mb, c) \
    asm volatile("mbarrier.init.shared.b64 [%0], %1;" :: "r"((uint32_t)(mb)), "r"((uint32_t)(c)) : "memory")
#define MBARRIER_EXPECT_TX(mb, b) \
    asm volatile("mbarrier.arrive.expect_tx.shared.b64 _, [%0], %1;" :: "r"((uint32_t)(mb)), "r"((uint32_t)(b)) : "memory")
#define MBARRIER_WAIT_PARITY(mb, ph) do { \
    uint32_t _m = (uint32_t)(mb), _p = (uint32_t)(ph), _d; \
    asm volatile("{ .reg .pred p; mbarrier.try_wait.parity.acquire.cta.shared::cta.b64 p, [%1], %2; selp.b32 %0,1,0,p; }" \
        : "=r"(_d) : "r"(_m), "r"(_p) : "memory"); \
    if (!_d) { \
        asm volatile("{ .reg .pred P1; WL_%=: mbarrier.try_wait.parity.acquire.cta.shared::cta.b64 P1, [%0], %1, 0x989680; @P1 bra.uni WD_%=; bra.uni WL_%=; WD_%=: }" \
            :: "r"(_m), "r"(_p) : "memory"); \
    } } while (0)
#define CP_ASYNC16Z(sdst, gsrc, sz) \
    asm volatile("cp.async.cg.shared.global [%0], [%1], 16, %2;" :: "r"(sdst), "l"(gsrc), "r"(sz) : "memory")
#define CP_ASYNC_COMMIT() asm volatile("cp.async.commit_group;" ::: "memory")
#define CP_ASYNC_WAIT0()  asm volatile("cp.async.wait_group 0;" ::: "memory")
#define CP_BULK(sdst, gsrc, bytes, mb) \
    asm volatile("cp.async.bulk.shared::cluster.global.mbarrier::complete_tx::bytes [%0], [%1], %2, [%3];" \
        :: "r"((uint32_t)(sdst)), "l"(gsrc), "r"((uint32_t)(bytes)), "r"((uint32_t)(mb)) : "memory")
#define LDSM_X4(r0, r1, r2, r3, a) \
    asm volatile("ldmatrix.sync.aligned.m8n8.x4.shared.b16 {%0,%1,%2,%3}, [%4];" \
        : "=r"(r0), "=r"(r1), "=r"(r2), "=r"(r3) : "r"(a))
#define MMA16816(d, av, bv) \
    asm volatile("mma.sync.aligned.m16n8k16.row.col.f32.f16.f16.f32 " \
        "{%0,%1,%2,%3}, {%4,%5,%6,%7}, {%8,%9}, {%0,%1,%2,%3};" \
        : "+f"((d)[0]), "+f"((d)[1]), "+f"((d)[2]), "+f"((d)[3]) \
        : "r"((av)[0]), "r"((av)[1]), "r"((av)[2]), "r"((av)[3]), "r"((bv)[0]), "r"((bv)[1]))

// ---------------------------------------------------------------------------
// XLA/Eigen rational tanh replica (bit-matching jnp.tanh — one weight-bin
// flip injects ~2e-3 rel_err).
// ---------------------------------------------------------------------------
__device__ __forceinline__ float xla_tanh(float x) {
    float ax = fabsf(x);
    if (ax < 0.0004f) return x;
    float xc = fminf(fmaxf(x, -7.90531110763549805f), 7.90531110763549805f);
    float x2 = xc * xc;
    float p = -2.76076847742355e-16f;
    p = fmaf(p, x2, 2.00018790482477e-13f);
    p = fmaf(p, x2, -8.60467152213735e-11f);
    p = fmaf(p, x2, 5.12229709037114e-08f);
    p = fmaf(p, x2, 1.48572235717979e-05f);
    p = fmaf(p, x2, 6.37261928875436e-04f);
    p = fmaf(p, x2, 4.89352455891786e-03f);
    p = p * xc;
    float q = 1.19825839466702e-06f;
    q = fmaf(q, x2, 1.18534705686654e-04f);
    q = fmaf(q, x2, 2.26843463243900e-03f);
    q = fmaf(q, x2, 4.89352518554385e-03f);
    return p / q;
}

// ---------------- prep kernels --------------------------------------------
__global__ void k_init(const float* __restrict__ gamma, const float* __restrict__ beta,
                       const float* __restrict__ mean,  const float* __restrict__ var) {
    int t = threadIdx.x;
    if (t == 0) g_max_bits = 0;
    float inv = gamma[t] / sqrtf(var[t] + 1e-5f);
    g_inv[t]  = inv;
    g_bias[t] = beta[t] - mean[t] * inv;
}

__global__ void k_max(const float* __restrict__ w) {
    __shared__ float sm[256];
    float m = 0.f;
    for (int i = blockIdx.x * 256 + threadIdx.x; i < NW; i += gridDim.x * 256)
        m = fmaxf(m, fabsf(xla_tanh(w[i])));
    sm[threadIdx.x] = m;
    __syncthreads();
    for (int s = 128; s > 0; s >>= 1) {
        if (threadIdx.x < s) sm[threadIdx.x] = fmaxf(sm[threadIdx.x], sm[threadIdx.x + s]);
        __syncthreads();
    }
    if (threadIdx.x == 0) atomicMax(&g_max_bits, __float_as_int(sm[0]));
}

// wq*15 = 2q-15 (odd int, exact fp16) -> blocks [(ci>>6)*9+tap][co][64],
// 16B-unit xor(co&7) baked so a linear bulk copy lands ldmatrix-conflict-free.
__global__ void k_quant16(const float* __restrict__ w) {
    int i = blockIdx.x * blockDim.x + threadIdx.x;
    if (i >= NW) return;
    float M = __int_as_float(g_max_bits);
    float t = xla_tanh(w[i]);
    t = t / (2.0f * M) + 0.5f;
    float q = rintf(t * 15.0f);
    int co = i / 2304;
    int r  = i % 2304;
    int ci = r / 9, tap = r % 9;
    int s  = (ci >> 6) * 9 + tap;
    int u0 = (ci & 63) >> 3;
    int pos = s * 16384 + co * 64 + ((u0 ^ (co & 7)) << 3) + (ci & 7);
    g_w15[pos] = __float2half(2.0f * q - 15.0f);
}

// split x into hi/lo fp16 planes, transposed to [n][pix][ci]
__global__ __launch_bounds__(256) void k_split(const float* __restrict__ x) {
    __shared__ float s[256][33];
    int n = blockIdx.y, px0 = blockIdx.x * 32, t = threadIdx.x;
    const float4* src = (const float4*)(x + ((size_t)(n * 256 + t)) * 3136 + px0);
#pragma unroll
    for (int i = 0; i < 8; i++) {
        float4 v = src[i];
        s[t][i*4+0] = v.x; s[t][i*4+1] = v.y; s[t][i*4+2] = v.z; s[t][i*4+3] = v.w;
    }
    __syncthreads();
    const int pl = t >> 3;
    const int c0 = (t & 7) * 4;
    __half* dh = g_xh + ((size_t)(n * 3136 + px0 + pl)) * 256;
    __half* dl = g_xl + ((size_t)(n * 3136 + px0 + pl)) * 256;
#pragma unroll
    for (int j = 0; j < 8; j++) {
        int cb = j * 32 + c0;
        uint32_t hb[2], lb[2];
#pragma unroll
        for (int c = 0; c < 4; c += 2) {
            float f0 = s[cb + c][pl], f1 = s[cb + c + 1][pl];
            __half h0 = __float2half(f0), h1 = __float2half(f1);
            __half l0 = __float2half(f0 - __half2float(h0));
            __half l1 = __float2half(f1 - __half2float(h1));
            hb[c >> 1] = (uint32_t)__half_as_ushort(h0) | ((uint32_t)__half_as_ushort(h1) << 16);
            lb[c >> 1] = (uint32_t)__half_as_ushort(l0) | ((uint32_t)__half_as_ushort(l1) << 16);
        }
        *(uint2*)(dh + cb) = make_uint2(hb[0], hb[1]);
        *(uint2*)(dl + cb) = make_uint2(lb[0], lb[1]);
    }
}

// ---------------------------------------------------------------------------
// Main conv kernel: implicit GEMM, split-fp16 exact, 8x8 pixel tiles (M=64,
// ZERO padding waste), N=256 co, 8 warps (warp tile 32x64), occupancy 2.
// 4 chunk-stages (64 ci): A halo patch (2 planes x 10x10 pix x 64ci) single-
// buffered cp.async; 9 taps via per-lane ldmatrix address shifts. B: per-tap
// cp.async.bulk, double-buffered via mbarriers.
// ---------------------------------------------------------------------------
#define A_PLANE  12800                 // 100 patch pixels * 128B
#define A_BUF    (2*A_PLANE)           // 25600 (both planes)
#define B_BUF    32768                 // 256 co * 128B
#define SMEM_BUF0 3072
#define DSMEM    (SMEM_BUF0 + A_BUF + 2*B_BUF)   // 94208

__global__ __launch_bounds__(256, 2)
void k_conv(const float* __restrict__ alpha, float* __restrict__ out) {
    extern __shared__ char smem[];
    const uint32_t sb = smem_u32(smem);
    const int t = threadIdx.x;
    const int lane = t & 31, wid = t >> 5;
    const int n = blockIdx.y;
    const int h0 = (blockIdx.x / 7) * 8, w0 = (blockIdx.x % 7) * 8;

    float* sInv  = (float*)(smem);
    float* sBias = (float*)(smem + 1024);
    const uint32_t mbA[2] = { sb + 2048, sb + 2056 };
    const uint32_t aBase = sb + SMEM_BUF0;
    const uint32_t bBase0 = sb + SMEM_BUF0 + A_BUF;

    if (t < 256) { sInv[t] = g_inv[t]; sBias[t] = g_bias[t]; }
    if (t == 0) { MBARRIER_INIT(mbA[0], 1); MBARRIER_INIT(mbA[1], 1); }
    __syncthreads();

    const int m0 = (wid & 1) * 32;        // warp M offset (pixels 0/32)
    const int n0 = (wid >> 1) * 64;       // warp N offset (co 0/64/128/192)
    const int g  = lane >> 2;
    const int tq = lane & 3;
    const int l7 = lane & 7, lq = lane >> 3;

    // A fragment base patch index (before tap shift): pixel -> (pr,pc) -> pr*10+pc
    int bp[2];
#pragma unroll
    for (int mt = 0; mt < 2; mt++) {
        int pix = m0 + mt * 16 + l7 + (lq & 1) * 8;    // 0..63
        bp[mt] = (pix >> 3) * 10 + (pix & 7);
    }
    // B fragment row bases
    uint32_t coB[4], coX[4];
#pragma unroll
    for (int ntp = 0; ntp < 4; ntp++) {
        int co = n0 + ntp * 16 + l7 + (lq >> 1) * 8;
        coB[ntp] = (uint32_t)co << 7;
        coX[ntp] = (uint32_t)(co & 7);
    }

    float acc[2][8][4];
#pragma unroll
    for (int a1 = 0; a1 < 2; a1++)
#pragma unroll
        for (int a2 = 0; a2 < 8; a2++)
#pragma unroll
            for (int a3 = 0; a3 < 4; a3++) acc[a1][a2][a3] = 0.f;

    const __half* gxp[2] = { g_xh, g_xl };

    // prologue: B block 0 prefetch
    if (t == 0) {
        MBARRIER_EXPECT_TX(mbA[0], B_BUF);
        CP_BULK(bBase0, (const void*)g_w15, B_BUF, mbA[0]);
    }

    for (int c = 0; c < 4; c++) {
        __syncthreads();                       // all reads of previous A done
        // ---- A patch: 100 pixels x 8 units x 2 planes = 1600 cp.async ----
        {
            const int ci0 = c * 64;
#pragma unroll
            for (int j = 0; j < 7; j++) {
                int i = t + j * 256;
                if (i < 1600) {
                    int u = i & 7, idx8 = i >> 3;       // 0..199
                    int pl = (idx8 >= 100) ? 1 : 0;
                    int p  = idx8 - pl * 100;           // 0..99
                    int pr = p / 10, pc = p - pr * 10;
                    int h2 = h0 - 1 + pr, w2 = w0 - 1 + pc;
                    bool valid = ((unsigned)h2 < 56u) && ((unsigned)w2 < 56u);
                    size_t o = valid ? (((size_t)(n * 3136 + h2 * 56 + w2)) * 256 + ci0 + u * 8) : 0;
                    uint32_t sdst = aBase + pl * A_PLANE + (p << 7) + (((u ^ (p & 7))) << 4);
                    CP_ASYNC16Z(sdst, gxp[pl] + o, valid ? 16u : 0u);
                }
            }
            CP_ASYNC_COMMIT();
            CP_ASYNC_WAIT0();
        }

        for (int tap = 0; tap < 9; tap++) {
            const int idx = c * 9 + tap;
            __syncthreads();                   // A visible; B[idx-1] reads done
            if (t == 0 && idx < 35) {
                uint32_t mb = mbA[(idx + 1) & 1];
                MBARRIER_EXPECT_TX(mb, B_BUF);
                CP_BULK(bBase0 + ((idx + 1) & 1) * B_BUF,
                        (const void*)(g_w15 + (size_t)(idx + 1) * 16384), B_BUF, mb);
            }
            MBARRIER_WAIT_PARITY(mbA[idx & 1], (idx >> 1) & 1);

            const uint32_t bBase = bBase0 + (idx & 1) * B_BUF;
            const int kh = tap / 3, kw = tap - kh * 3;
            const int tapAdd = kh * 10 + kw;

#pragma unroll
            for (int k16 = 0; k16 < 4; k16++) {
                uint32_t bf[8][2];
#pragma unroll
                for (int ntp = 0; ntp < 4; ntp++) {
                    uint32_t ba = bBase + coB[ntp]
                                + ((((uint32_t)(k16 * 2) + (lq & 1)) ^ coX[ntp]) << 4);
                    LDSM_X4(bf[2*ntp][0], bf[2*ntp][1], bf[2*ntp+1][0], bf[2*ntp+1][1], ba);
                }
#pragma unroll
                for (int pl = 0; pl < 2; pl++) {
#pragma unroll
                    for (int mt = 0; mt < 2; mt++) {
                        int p = bp[mt] + tapAdd;
                        uint32_t aa = aBase + pl * A_PLANE + ((uint32_t)p << 7)
                                    + ((((uint32_t)(k16 * 2) + (lq >> 1)) ^ (uint32_t)(p & 7)) << 4);
                        uint32_t av[4];
                        LDSM_X4(av[0], av[1], av[2], av[3], aa);
#pragma unroll
                        for (int nt = 0; nt < 8; nt++)
                            MMA16816(acc[mt][nt], av, bf[nt]);
                    }
                }
            }
        }
    }

    // ---- epilogue: /15 -> BN -> PACT -> store (all pixels valid) ----
    const float a = alpha[0];
    const float stepq = a / 15.0f;
#pragma unroll
    for (int mt = 0; mt < 2; mt++) {
#pragma unroll
        for (int nt = 0; nt < 8; nt++) {
#pragma unroll
            for (int e = 0; e < 4; e++) {
                int pix = m0 + mt * 16 + g + (e >> 1) * 8;
                int co  = n0 + nt * 8 + tq * 2 + (e & 1);
                int hh = h0 + (pix >> 3), ww = w0 + (pix & 7);
                float y = acc[mt][nt][e] * (1.0f / 15.0f);
                float v = y * sInv[co] + sBias[co];
                v = fminf(fmaxf(v, 0.f), a);
                float q = rintf(v * 15.0f / a);
                out[((size_t)(n * 256 + co)) * 3136 + hh * 56 + ww] = q * stepq;
            }
        }
    }
}

// ---------------------------------------------------------------------------
extern "C" void kernel_launch(void* const* d_in, const int* in_sizes, int n_in,
                              void* d_out, int out_size) {
    const float* x     = (const float*)d_in[0];
    const float* w     = (const float*)d_in[1];
    const float* gamma = (const float*)d_in[2];
    const float* beta  = (const float*)d_in[3];
    const float* mean  = (const float*)d_in[4];
    const float* var   = (const float*)d_in[5];
    const float* alpha = (const float*)d_in[6];
    float* out = (float*)d_out;

    static bool attr_set = false;
    if (!attr_set) {
        cudaFuncSetAttribute(k_conv, cudaFuncAttributeMaxDynamicSharedMemorySize, DSMEM);
        attr_set = true;
    }

    k_init<<<1, 256>>>(gamma, beta, mean, var);
    k_max<<<148, 256>>>(w);
    k_quant16<<<2304, 256>>>(w);
    k_split<<<dim3(98, 32), 256>>>(x);
    k_conv<<<dim3(49, 32), 256, DSMEM>>>(alpha, out);
}

// round 11
// speedup vs baseline: 6.8501x; 1.0303x over previous
#include <cuda_runtime.h>
#include <cuda_fp16.h>
#include <cstdint>

#define NW (256*256*9)

// ---------------- scratch (device globals; no allocation allowed) ----------
__device__ float  g_inv[256];
__device__ float  g_bias[256];
__device__ int    g_max_bits;
// B: 36 blocks [chunk*9+tap][256 co][64 halfs], 16B-unit xor (co&7) baked in
__device__ __align__(16) __half g_w15[36*256*64];
__device__ __align__(16) __half g_xh[32*3136*256];    // [n][pix][ci] hi plane
__device__ __align__(16) __half g_xl[32*3136*256];    // [n][pix][ci] lo plane

// ---------------- PTX helpers ---------------------------------------------
__device__ __forceinline__ uint32_t smem_u32(const void* p) {
    uint32_t a;
    asm("{ .reg .u64 t; cvta.to.shared.u64 t, %1; cvt.u32.u64 %0, t; }" : "=r"(a) : "l"(p));
    return a;
}
#define MBARRIER_INIT(mb, c) \
    asm volatile("mbarrier.init.shared.b64 [%0], %1;" :: "r"((uint32_t)(mb)), "r"((uint32_t)(c)) : "memory")
#define MBARRIER_EXPECT_TX(mb, b) \
    asm volatile("mbarrier.arrive.expect_tx.shared.b64 _, [%0], %1;" :: "r"((uint32_t)(mb)), "r"((uint32_t)(b)) : "memory")
#define MBARRIER_WAIT_PARITY(mb, ph) do { \
    uint32_t _m = (uint32_t)(mb), _p = (uint32_t)(ph), _d; \
    asm volatile("{ .reg .pred p; mbarrier.try_wait.parity.acquire.cta.shared::cta.b64 p, [%1], %2; selp.b32 %0,1,0,p; }" \
        : "=r"(_d) : "r"(_m), "r"(_p) : "memory"); \
    if (!_d) { \
        asm volatile("{ .reg .pred P1; WL_%=: mbarrier.try_wait.parity.acquire.cta.shared::cta.b64 P1, [%0], %1, 0x989680; @P1 bra.uni WD_%=; bra.uni WL_%=; WD_%=: }" \
            :: "r"(_m), "r"(_p) : "memory"); \
    } } while (0)
#define CP_ASYNC16Z(sdst, gsrc, sz) \
    asm volatile("cp.async.cg.shared.global [%0], [%1], 16, %2;" :: "r"(sdst), "l"(gsrc), "r"(sz) : "memory")
#define CP_ASYNC_COMMIT() asm volatile("cp.async.commit_group;" ::: "memory")
#define CP_ASYNC_WAIT0()  asm volatile("cp.async.wait_group 0;" ::: "memory")
#define CP_BULK(sdst, gsrc, bytes, mb) \
    asm volatile("cp.async.bulk.shared::cluster.global.mbarrier::complete_tx::bytes [%0], [%1], %2, [%3];" \
        :: "r"((uint32_t)(sdst)), "l"(gsrc), "r"((uint32_t)(bytes)), "r"((uint32_t)(mb)) : "memory")
#define LDSM_X4(r0, r1, r2, r3, a) \
    asm volatile("ldmatrix.sync.aligned.m8n8.x4.shared.b16 {%0,%1,%2,%3}, [%4];" \
        : "=r"(r0), "=r"(r1), "=r"(r2), "=r"(r3) : "r"(a))
#define MMA16816(d, av, bv) \
    asm volatile("mma.sync.aligned.m16n8k16.row.col.f32.f16.f16.f32 " \
        "{%0,%1,%2,%3}, {%4,%5,%6,%7}, {%8,%9}, {%0,%1,%2,%3};" \
        : "+f"((d)[0]), "+f"((d)[1]), "+f"((d)[2]), "+f"((d)[3]) \
        : "r"((av)[0]), "r"((av)[1]), "r"((av)[2]), "r"((av)[3]), "r"((bv)[0]), "r"((bv)[1]))

// ---------------------------------------------------------------------------
// XLA/Eigen rational tanh replica (bit-matching jnp.tanh — one weight-bin
// flip injects ~2e-3 rel_err).
// ---------------------------------------------------------------------------
__device__ __forceinline__ float xla_tanh(float x) {
    float ax = fabsf(x);
    if (ax < 0.0004f) return x;
    float xc = fminf(fmaxf(x, -7.90531110763549805f), 7.90531110763549805f);
    float x2 = xc * xc;
    float p = -2.76076847742355e-16f;
    p = fmaf(p, x2, 2.00018790482477e-13f);
    p = fmaf(p, x2, -8.60467152213735e-11f);
    p = fmaf(p, x2, 5.12229709037114e-08f);
    p = fmaf(p, x2, 1.48572235717979e-05f);
    p = fmaf(p, x2, 6.37261928875436e-04f);
    p = fmaf(p, x2, 4.89352455891786e-03f);
    p = p * xc;
    float q = 1.19825839466702e-06f;
    q = fmaf(q, x2, 1.18534705686654e-04f);
    q = fmaf(q, x2, 2.26843463243900e-03f);
    q = fmaf(q, x2, 4.89352518554385e-03f);
    return p / q;
}

// ---------------- prep kernels --------------------------------------------
// k_maxinit: global max |tanh(w)| reduction; block 0 also precomputes BN
// inv/bias (merged k_init to cut a launch).
__global__ void k_maxinit(const float* __restrict__ w,
                          const float* __restrict__ gamma, const float* __restrict__ beta,
                          const float* __restrict__ mean,  const float* __restrict__ var) {
    __shared__ float sm[256];
    int t = threadIdx.x;
    if (blockIdx.x == 0) {
        if (t == 0) g_max_bits = 0;
        float inv = gamma[t] / sqrtf(var[t] + 1e-5f);
        g_inv[t]  = inv;
        g_bias[t] = beta[t] - mean[t] * inv;
    }
    float m = 0.f;
    for (int i = blockIdx.x * 256 + t; i < NW; i += gridDim.x * 256)
        m = fmaxf(m, fabsf(xla_tanh(w[i])));
    sm[t] = m;
    __syncthreads();
    for (int s = 128; s > 0; s >>= 1) {
        if (t < s) sm[t] = fmaxf(sm[t], sm[t + s]);
        __syncthreads();
    }
    if (t == 0) atomicMax(&g_max_bits, __float_as_int(sm[0]));
}

// wq*15 = 2q-15 (odd int, exact fp16) -> blocks [(ci>>6)*9+tap][co][64],
// 16B-unit xor(co&7) baked so a linear bulk copy lands ldmatrix-conflict-free.
__global__ void k_quant16(const float* __restrict__ w) {
    int i = blockIdx.x * blockDim.x + threadIdx.x;
    if (i >= NW) return;
    float M = __int_as_float(g_max_bits);
    float t = xla_tanh(w[i]);
    t = t / (2.0f * M) + 0.5f;
    float q = rintf(t * 15.0f);
    int co = i / 2304;
    int r  = i % 2304;
    int ci = r / 9, tap = r % 9;
    int s  = (ci >> 6) * 9 + tap;
    int u0 = (ci & 63) >> 3;
    int pos = s * 16384 + co * 64 + ((u0 ^ (co & 7)) << 3) + (ci & 7);
    g_w15[pos] = __float2half(2.0f * q - 15.0f);
}

// split x into hi/lo fp16 planes, transposed to [n][pix][ci].
// 64 pixels per block; both 32-pixel groups' loads issued up front (16 LDG.128
// in flight) and drained through one smem buffer in two phases.
__global__ __launch_bounds__(256) void k_split(const float* __restrict__ x) {
    __shared__ float s[256][33];
    int n = blockIdx.y, px0 = blockIdx.x * 64, t = threadIdx.x;
    const float4* src = (const float4*)(x + ((size_t)(n * 256 + t)) * 3136 + px0);
    float4 r0[8], r1[8];
#pragma unroll
    for (int i = 0; i < 8; i++) r0[i] = src[i];
#pragma unroll
    for (int i = 0; i < 8; i++) r1[i] = src[8 + i];

    const int pl = t >> 3;
    const int c0 = (t & 7) * 4;

#pragma unroll
    for (int grp = 0; grp < 2; grp++) {
        const float4* rr = grp ? r1 : r0;
        if (grp) __syncthreads();     // phase-0 readers done before overwrite
#pragma unroll
        for (int i = 0; i < 8; i++) {
            float4 v = rr[i];
            s[t][i*4+0] = v.x; s[t][i*4+1] = v.y; s[t][i*4+2] = v.z; s[t][i*4+3] = v.w;
        }
        __syncthreads();
        __half* dh = g_xh + ((size_t)(n * 3136 + px0 + grp * 32 + pl)) * 256;
        __half* dl = g_xl + ((size_t)(n * 3136 + px0 + grp * 32 + pl)) * 256;
#pragma unroll
        for (int j = 0; j < 8; j++) {
            int cb = j * 32 + c0;
            uint32_t hb[2], lb[2];
#pragma unroll
            for (int c = 0; c < 4; c += 2) {
                float f0 = s[cb + c][pl], f1 = s[cb + c + 1][pl];
                __half h0 = __float2half(f0), h1 = __float2half(f1);
                __half l0 = __float2half(f0 - __half2float(h0));
                __half l1 = __float2half(f1 - __half2float(h1));
                hb[c >> 1] = (uint32_t)__half_as_ushort(h0) | ((uint32_t)__half_as_ushort(h1) << 16);
                lb[c >> 1] = (uint32_t)__half_as_ushort(l0) | ((uint32_t)__half_as_ushort(l1) << 16);
            }
            *(uint2*)(dh + cb) = make_uint2(hb[0], hb[1]);
            *(uint2*)(dl + cb) = make_uint2(lb[0], lb[1]);
        }
    }
}

// ---------------------------------------------------------------------------
// Main conv kernel: implicit GEMM, split-fp16 exact, 8x8 pixel tiles (M=64,
// ZERO padding waste), N=256 co, 8 warps (warp tile 32x64), occupancy 2.
// 4 chunk-stages (64 ci): A halo patch (2 planes x 10x10 pix x 64ci) single-
// buffered cp.async; 9 taps via per-lane ldmatrix address shifts. B: per-tap
// cp.async.bulk, double-buffered via mbarriers.
// ---------------------------------------------------------------------------
#define A_PLANE  12800                 // 100 patch pixels * 128B
#define A_BUF    (2*A_PLANE)           // 25600 (both planes)
#define B_BUF    32768                 // 256 co * 128B
#define SMEM_BUF0 3072
#define DSMEM    (SMEM_BUF0 + A_BUF + 2*B_BUF)   // 94208

__global__ __launch_bounds__(256, 2)
void k_conv(const float* __restrict__ alpha, float* __restrict__ out) {
    extern __shared__ char smem[];
    const uint32_t sb = smem_u32(smem);
    const int t = threadIdx.x;
    const int lane = t & 31, wid = t >> 5;
    const int n = blockIdx.y;
    const int h0 = (blockIdx.x / 7) * 8, w0 = (blockIdx.x % 7) * 8;

    float* sInv  = (float*)(smem);
    float* sBias = (float*)(smem + 1024);
    const uint32_t mbA[2] = { sb + 2048, sb + 2056 };
    const uint32_t aBase = sb + SMEM_BUF0;
    const uint32_t bBase0 = sb + SMEM_BUF0 + A_BUF;

    if (t < 256) { sInv[t] = g_inv[t]; sBias[t] = g_bias[t]; }
    if (t == 0) { MBARRIER_INIT(mbA[0], 1); MBARRIER_INIT(mbA[1], 1); }
    __syncthreads();

    const int m0 = (wid & 1) * 32;        // warp M offset (pixels 0/32)
    const int n0 = (wid >> 1) * 64;       // warp N offset (co 0/64/128/192)
    const int g  = lane >> 2;
    const int tq = lane & 3;
    const int l7 = lane & 7, lq = lane >> 3;

    // A fragment base patch index (before tap shift): pixel -> (pr,pc) -> pr*10+pc
    int bp[2];
#pragma unroll
    for (int mt = 0; mt < 2; mt++) {
        int pix = m0 + mt * 16 + l7 + (lq & 1) * 8;    // 0..63
        bp[mt] = (pix >> 3) * 10 + (pix & 7);
    }
    // B fragment row bases
    uint32_t coB[4], coX[4];
#pragma unroll
    for (int ntp = 0; ntp < 4; ntp++) {
        int co = n0 + ntp * 16 + l7 + (lq >> 1) * 8;
        coB[ntp] = (uint32_t)co << 7;
        coX[ntp] = (uint32_t)(co & 7);
    }

    float acc[2][8][4];
#pragma unroll
    for (int a1 = 0; a1 < 2; a1++)
#pragma unroll
        for (int a2 = 0; a2 < 8; a2++)
#pragma unroll
            for (int a3 = 0; a3 < 4; a3++) acc[a1][a2][a3] = 0.f;

    const __half* gxp[2] = { g_xh, g_xl };

    // prologue: B block 0 prefetch
    if (t == 0) {
        MBARRIER_EXPECT_TX(mbA[0], B_BUF);
        CP_BULK(bBase0, (const void*)g_w15, B_BUF, mbA[0]);
    }

    for (int c = 0; c < 4; c++) {
        __syncthreads();                       // all reads of previous A done
        // ---- A patch: 100 pixels x 8 units x 2 planes = 1600 cp.async ----
        {
            const int ci0 = c * 64;
#pragma unroll
            for (int j = 0; j < 7; j++) {
                int i = t + j * 256;
                if (i < 1600) {
                    int u = i & 7, idx8 = i >> 3;       // 0..199
                    int pl = (idx8 >= 100) ? 1 : 0;
                    int p  = idx8 - pl * 100;           // 0..99
                    int pr = p / 10, pc = p - pr * 10;
                    int h2 = h0 - 1 + pr, w2 = w0 - 1 + pc;
                    bool valid = ((unsigned)h2 < 56u) && ((unsigned)w2 < 56u);
                    size_t o = valid ? (((size_t)(n * 3136 + h2 * 56 + w2)) * 256 + ci0 + u * 8) : 0;
                    uint32_t sdst = aBase + pl * A_PLANE + (p << 7) + (((u ^ (p & 7))) << 4);
                    CP_ASYNC16Z(sdst, gxp[pl] + o, valid ? 16u : 0u);
                }
            }
            CP_ASYNC_COMMIT();
            CP_ASYNC_WAIT0();
        }

        for (int tap = 0; tap < 9; tap++) {
            const int idx = c * 9 + tap;
            __syncthreads();                   // A visible; B[idx-1] reads done
            if (t == 0 && idx < 35) {
                uint32_t mb = mbA[(idx + 1) & 1];
                MBARRIER_EXPECT_TX(mb, B_BUF);
                CP_BULK(bBase0 + ((idx + 1) & 1) * B_BUF,
                        (const void*)(g_w15 + (size_t)(idx + 1) * 16384), B_BUF, mb);
            }
            MBARRIER_WAIT_PARITY(mbA[idx & 1], (idx >> 1) & 1);

            const uint32_t bBase = bBase0 + (idx & 1) * B_BUF;
            const int kh = tap / 3, kw = tap - kh * 3;
            const int tapAdd = kh * 10 + kw;

#pragma unroll
            for (int k16 = 0; k16 < 4; k16++) {
                uint32_t bf[8][2];
#pragma unroll
                for (int ntp = 0; ntp < 4; ntp++) {
                    uint32_t ba = bBase + coB[ntp]
                                + ((((uint32_t)(k16 * 2) + (lq & 1)) ^ coX[ntp]) << 4);
                    LDSM_X4(bf[2*ntp][0], bf[2*ntp][1], bf[2*ntp+1][0], bf[2*ntp+1][1], ba);
                }
#pragma unroll
                for (int pl = 0; pl < 2; pl++) {
#pragma unroll
                    for (int mt = 0; mt < 2; mt++) {
                        int p = bp[mt] + tapAdd;
                        uint32_t aa = aBase + pl * A_PLANE + ((uint32_t)p << 7)
                                    + ((((uint32_t)(k16 * 2) + (lq >> 1)) ^ (uint32_t)(p & 7)) << 4);
                        uint32_t av[4];
                        LDSM_X4(av[0], av[1], av[2], av[3], aa);
#pragma unroll
                        for (int nt = 0; nt < 8; nt++)
                            MMA16816(acc[mt][nt], av, bf[nt]);
                    }
                }
            }
        }
    }

    // ---- epilogue: /15 -> BN -> PACT -> store (all pixels valid) ----
    const float a = alpha[0];
    const float stepq = a / 15.0f;
#pragma unroll
    for (int mt = 0; mt < 2; mt++) {
#pragma unroll
        for (int nt = 0; nt < 8; nt++) {
#pragma unroll
            for (int e = 0; e < 4; e++) {
                int pix = m0 + mt * 16 + g + (e >> 1) * 8;
                int co  = n0 + nt * 8 + tq * 2 + (e & 1);
                int hh = h0 + (pix >> 3), ww = w0 + (pix & 7);
                float y = acc[mt][nt][e] * (1.0f / 15.0f);
                float v = y * sInv[co] + sBias[co];
                v = fminf(fmaxf(v, 0.f), a);
                float q = rintf(v * 15.0f / a);
                out[((size_t)(n * 256 + co)) * 3136 + hh * 56 + ww] = q * stepq;
            }
        }
    }
}

// ---------------------------------------------------------------------------
extern "C" void kernel_launch(void* const* d_in, const int* in_sizes, int n_in,
                              void* d_out, int out_size) {
    const float* x     = (const float*)d_in[0];
    const float* w     = (const float*)d_in[1];
    const float* gamma = (const float*)d_in[2];
    const float* beta  = (const float*)d_in[3];
    const float* mean  = (const float*)d_in[4];
    const float* var   = (const float*)d_in[5];
    const float* alpha = (const float*)d_in[6];
    float* out = (float*)d_out;

    static bool attr_set = false;
    if (!attr_set) {
        cudaFuncSetAttribute(k_conv, cudaFuncAttributeMaxDynamicSharedMemorySize, DSMEM);
        attr_set = true;
    }

    // Order puts k_conv at the 4th launch slot (where ncu has been sampling).
    k_split<<<dim3(49, 32), 256>>>(x);
    k_maxinit<<<148, 256>>>(w, gamma, beta, mean, var);
    k_quant16<<<2304, 256>>>(w);
    k_conv<<<dim3(49, 32), 256, DSMEM>>>(alpha, out);
}